// round 14
// baseline (speedup 1.0000x reference)
#include <cuda_runtime.h>
#include <math.h>

#define BB 16
#define CC 3
#define HH 512
#define WW 512
#define HWv (HH*WW)

#define TXW 128
#define TYH 8
#define XT (WW/TXW)           // 4
#define YT (HH/TYH)           // 64
#define NBLK (BB*XT*YT)       // 4096
#define NT 256
#define PITCH 136             // col 3 = x-1 halo, 4..131 interior, 132 = x+128 halo

#define IRBLK 128
#define NIRB (BB*IRBLK)       // 2048

__device__ double   g_ir_part[NIRB];
__device__ float    g_part[NBLK];
__device__ unsigned g_done = 0;

// ---------------------------------------------------------------------------
// 1) per-batch gray sum of input_ir. gray = 0.2989 R + 0.587 G + 0.114 B
// ---------------------------------------------------------------------------
__global__ __launch_bounds__(256)
void ir_mean_kernel(const float4* __restrict__ ir) {
    int b   = blockIdx.x / IRBLK;
    int blk = blockIdx.x % IRBLK;
    const int q4  = HWv / 4;
    const int per = q4 / IRBLK;       // 512 float4 per block

    size_t base = (size_t)b * CC * q4 + (size_t)blk * per;
    const float4* r  = ir + base;
    const float4* g  = r + q4;
    const float4* bl = g + q4;

    float s = 0.f;
    #pragma unroll 2
    for (int i = threadIdx.x; i < per; i += 256) {
        float4 a = r[i], c = g[i], d = bl[i];
        s += 0.2989f * (a.x + a.y + a.z + a.w)
           + 0.587f  * (c.x + c.y + c.z + c.w)
           + 0.114f  * (d.x + d.y + d.z + d.w);
    }
    #pragma unroll
    for (int o = 16; o; o >>= 1) s += __shfl_down_sync(0xffffffffu, s, o);

    __shared__ float ws[8];
    int wid = threadIdx.x >> 5, lid = threadIdx.x & 31;
    if (lid == 0) ws[wid] = s;
    __syncthreads();
    if (wid == 0) {
        s = (lid < 8) ? ws[lid] : 0.f;
        #pragma unroll
        for (int o = 4; o; o >>= 1) s += __shfl_down_sync(0xffffffffu, s, o);
        if (lid == 0) g_ir_part[blockIdx.x] = (double)s;
    }
}

__device__ __forceinline__ float clip01(float x) {
    return fminf(fmaxf(x, 0.f), 1.f);
}

// Sobel gx/gy for 4 horizontal pixels from one smem plane.
// 3 float4 LDS (rows rbase..rbase+2), vertical partials in registers,
// horizontal T/S halo via warp shuffle; edge lanes read smem halo columns.
// (numerically verified in R9)
__device__ __forceinline__ void field_grad(const float* __restrict__ pl,
                                           int rbase, int cm, int lane,
                                           float gx[4], float gy[4], float ctr[4]) {
    const float* r0 = pl + rbase * PITCH + cm;
    const float* r1 = r0 + PITCH;
    const float* r2 = r1 + PITCH;
    float4 a = *(const float4*)r0;
    float4 b = *(const float4*)r1;
    float4 d = *(const float4*)r2;

    float T1 = a.x + 2.f*b.x + d.x, S1 = a.x - d.x;
    float T2 = a.y + 2.f*b.y + d.y, S2 = a.y - d.y;
    float T3 = a.z + 2.f*b.z + d.z, S3 = a.z - d.z;
    float T4 = a.w + 2.f*b.w + d.w, S4 = a.w - d.w;

    float Tl = 0.f, Sl = 0.f, Tr = 0.f, Sr = 0.f;
    if (lane == 0) {
        const float* h = pl + rbase * PITCH + 3;
        float e0 = h[0], e1 = h[PITCH], e2 = h[2*PITCH];
        Tl = e0 + 2.f*e1 + e2;  Sl = e0 - e2;
    }
    if (lane == 31) {
        const float* h = pl + rbase * PITCH + (4 + TXW);
        float e0 = h[0], e1 = h[PITCH], e2 = h[2*PITCH];
        Tr = e0 + 2.f*e1 + e2;  Sr = e0 - e2;
    }
    float tu = __shfl_up_sync(0xffffffffu, T4, 1);
    float su = __shfl_up_sync(0xffffffffu, S4, 1);
    float td = __shfl_down_sync(0xffffffffu, T1, 1);
    float sd = __shfl_down_sync(0xffffffffu, S1, 1);
    float T0 = lane ? tu : Tl;
    float S0 = lane ? su : Sl;
    float T5 = (lane < 31) ? td : Tr;
    float S5 = (lane < 31) ? sd : Sr;

    gx[0] = T2 - T0;  gx[1] = T3 - T1;  gx[2] = T4 - T2;  gx[3] = T5 - T3;
    gy[0] = S0 + 2.f*S1 + S2;  gy[1] = S1 + 2.f*S2 + S3;
    gy[2] = S2 + 2.f*S3 + S4;  gy[3] = S3 + 2.f*S4 + S5;
    ctr[0] = b.x;  ctr[1] = b.y;  ctr[2] = b.z;  ctr[3] = b.w;
}

// ---------------------------------------------------------------------------
// 2) fused main pass: 128x8 tiles, per-channel load/compute phases,
//    shuffle-based stencil compute (I -> V -> F with immediate folding).
// ---------------------------------------------------------------------------
__global__ __launch_bounds__(NT, 4)
void fusion_main_kernel(const float* __restrict__ vis,
                        const float* __restrict__ ir,
                        const float* __restrict__ outp,
                        const float* __restrict__ mask,
                        float* __restrict__ out) {
    __shared__ __align__(16) float sF[(TYH + 2) * PITCH];
    __shared__ __align__(16) float sV[(TYH + 2) * PITCH];
    __shared__ __align__(16) float sI[(TYH + 2) * PITCH];
    __shared__ double dred[4];
    __shared__ float  s_mean;
    __shared__ float  ws[NT / 32];
    __shared__ double wd[NT / 32];
    __shared__ bool   s_last;

    const int tid = threadIdx.x;
    const int bx  = blockIdx.x;
    const int b   = bx >> 8;              // 256 tiles per batch
    const int rem = bx & 255;
    const int y0  = (rem >> 2) * TYH;
    const int w0  = (rem & 3) * TXW;

    // per-batch IR mean from 128 partials
    if (tid < IRBLK) {
        double s = g_ir_part[b * IRBLK + tid];
        #pragma unroll
        for (int o = 16; o; o >>= 1) s += __shfl_down_sync(0xffffffffu, s, o);
        if ((tid & 31) == 0) dred[tid >> 5] = s;
    }
    __syncthreads();
    if (tid == 0)
        s_mean = (float)((dred[0] + dred[1] + dred[2] + dred[3]) * (1.0 / (double)HWv));
    __syncthreads();
    const float meanb = s_mean;

    const int row  = tid >> 5;            // warp id = pixel row 0..7
    const int lane = tid & 31;
    const int cm   = 4 + lane * 4;        // aligned interior float4 column

    float con = 0.f, gsum = 0.f, color = 0.f;
    float d0[4], dyk[4];

    #pragma unroll
    for (int c = 0; c < CC; c++) {
        const size_t pbase = ((size_t)b * CC + c) * HWv;

        // ---- load 10x128 interior (float4) + 10x2 halo scalars ----
        for (int idx = tid; idx < 340; idx += NT) {
            if (idx < 320) {
                int hy = idx >> 5, k = idx & 31;
                int y = y0 - 1 + hy;
                float4 f = make_float4(0.f, 0.f, 0.f, 0.f), v = f, q = f;
                if ((unsigned)y < HH) {
                    size_t rowp = pbase + (size_t)y * WW + w0;
                    float4 a  = ((const float4*)(outp + rowp))[k];
                    float4 m  = ((const float4*)(mask + rowp))[k];
                    float4 vv = ((const float4*)(vis  + rowp))[k];
                    float4 qq = ((const float4*)(ir   + rowp))[k];
                    f = make_float4(a.x * m.x, a.y * m.y, a.z * m.z, a.w * m.w);
                    v = make_float4(clip01(sqrtf(vv.x)), clip01(sqrtf(vv.y)),
                                    clip01(sqrtf(vv.z)), clip01(sqrtf(vv.w)));
                    q = make_float4(clip01(1.8f * qq.x - 0.8f * meanb),
                                    clip01(1.8f * qq.y - 0.8f * meanb),
                                    clip01(1.8f * qq.z - 0.8f * meanb),
                                    clip01(1.8f * qq.w - 0.8f * meanb));
                }
                int off = hy * PITCH + 4 + 4 * k;
                *(float4*)&sF[off] = f;
                *(float4*)&sV[off] = v;
                *(float4*)&sI[off] = q;
            } else {
                int j = idx - 320;
                int hy = j >> 1, side = j & 1;
                int y = y0 - 1 + hy;
                int x = side ? (w0 + TXW) : (w0 - 1);
                float f = 0.f, v = 0.f, q = 0.f;
                if ((unsigned)y < HH && (unsigned)x < WW) {
                    size_t p = pbase + (size_t)y * WW + x;
                    f = outp[p] * mask[p];
                    v = clip01(sqrtf(vis[p]));
                    q = clip01(1.8f * ir[p] - 0.8f * meanb);
                }
                int off = hy * PITCH + (side ? (4 + TXW) : 3);
                sF[off] = f;  sV[off] = v;  sI[off] = q;
            }
        }
        __syncthreads();

        // ---- compute: I, then V (fold max), then F (fold to scalars) ----
        {
            float jgx[4], jgy[4], Jc[4];           // joint (starts as I)
            field_grad(sI, row, cm, lane, jgx, jgy, Jc);

            float vgx[4], vgy[4], Vc[4];
            field_grad(sV, row, cm, lane, vgx, vgy, Vc);
            #pragma unroll
            for (int j = 0; j < 4; j++) {
                jgx[j] = fmaxf(jgx[j], vgx[j]);
                jgy[j] = fmaxf(jgy[j], vgy[j]);
                Jc[j]  = fmaxf(Jc[j],  Vc[j]);
            }

            float fgx[4], fgy[4], Fc[4];
            field_grad(sF, row, cm, lane, fgx, fgy, Fc);
            #pragma unroll
            for (int j = 0; j < 4; j++) {
                gsum += fabsf(fgx[j] - jgx[j]) + fabsf(fgy[j] - jgy[j]);
                con  += fabsf(Fc[j] - Jc[j]);
                float d = Fc[j] - Vc[j];
                if (c == 0)      { d0[j] = d; dyk[j] = 0.299f * d; }
                else if (c == 1) { dyk[j] += 0.587f * d; }
                else {
                    float dyt = dyk[j] + 0.114f * d;
                    color += 0.564f * fabsf(d - dyt) + 0.713f * fabsf(d0[j] - dyt);
                }
            }
        }
        __syncthreads();
    }

    const float inv3 = 1.0f / (float)(BB * CC * HWv);
    const float inv1 = 1.0f / (float)(BB * HWv);
    float acc = inv3 * (0.5f * con + 0.1f * gsum) + inv1 * color;

    // block reduction -> per-block partial
    #pragma unroll
    for (int o = 16; o; o >>= 1) acc += __shfl_down_sync(0xffffffffu, acc, o);
    int wid = tid >> 5, lid = tid & 31;
    if (lid == 0) ws[wid] = acc;
    __syncthreads();
    if (wid == 0) {
        acc = (lid < NT / 32) ? ws[lid] : 0.f;
        #pragma unroll
        for (int o = 4; o; o >>= 1) acc += __shfl_down_sync(0xffffffffu, acc, o);
        if (lid == 0) g_part[bx] = acc;
    }

    // fused finalize: last block sums all partials
    __threadfence();
    if (tid == 0) s_last = (atomicAdd(&g_done, 1u) == NBLK - 1);
    __syncthreads();
    if (s_last) {
        double s = 0.0;
        #pragma unroll
        for (int i = 0; i < NBLK / NT; i++) s += (double)g_part[tid + i * NT];
        #pragma unroll
        for (int o = 16; o; o >>= 1) s += __shfl_down_sync(0xffffffffu, s, o);
        if (lid == 0) wd[wid] = s;
        __syncthreads();
        if (wid == 0) {
            s = (lid < NT / 32) ? wd[lid] : 0.0;
            #pragma unroll
            for (int o = 4; o; o >>= 1) s += __shfl_down_sync(0xffffffffu, s, o);
            if (lid == 0) { out[0] = (float)s; g_done = 0; }
        }
    }
}

extern "C" void kernel_launch(void* const* d_in, const int* in_sizes, int n_in,
                              void* d_out, int out_size) {
    const float* vis  = (const float*)d_in[0];
    const float* ir   = (const float*)d_in[1];
    const float* outp = (const float*)d_in[2];
    const float* mask = (const float*)d_in[3];
    float* out = (float*)d_out;

    ir_mean_kernel<<<NIRB, 256>>>((const float4*)ir);
    fusion_main_kernel<<<NBLK, NT>>>(vis, ir, outp, mask, out);
}